// round 5
// baseline (speedup 1.0000x reference)
#include <cuda_runtime.h>
#include <cuda_bf16.h>
#include <cstdint>

#define NN 50000
#define EE 800000
#define REGSZ (NN * 128)
#define CHUNK 512
#define NCHUNK ((NN + CHUNK - 1) / CHUNK)   // 98

// ---------------- scratch (static device globals; no runtime alloc) ----------
__device__ int   g_deg[4 * NN];
__device__ int   g_cursor[4 * NN];
__device__ int   g_rowptr[4 * (NN + 1)];
__device__ float g_dinv[4 * NN];
__device__ int   g_csr_src[4 * EE];
__device__ float g_csr_coef[4 * EE];
__device__ float g_xw1[NN * 256];
__device__ float g_xw2[NN * 128];
__device__ int   g_is64[4];
__device__ int   g_chunksum[4 * NCHUNK];
__device__ int   g_chunkoff[4 * NCHUNK];
// bf16-split buffers: per-input X (4x), hidden H, weights (transposed [n][k])
__device__ __nv_bfloat16 g_Xhi[4][NN * 256];
__device__ __nv_bfloat16 g_Xlo[4][NN * 256];
__device__ __nv_bfloat16 g_Hhi[NN * 256];
__device__ __nv_bfloat16 g_Hlo[NN * 256];
#define WOFF1(p) ((p) * 65536)
#define WOFF2(p) (262144 + (p) * 32768)
#define WOFFR(i) (393216 + (i) * 32768)
__device__ __nv_bfloat16 g_Whi[458752];
__device__ __nv_bfloat16 g_Wlo[458752];

// ---------------- mma.sync / cp.async helpers --------------------------------
__device__ __forceinline__ uint32_t smem_u32(const void* p) {
    uint32_t a;
    asm("{ .reg .u64 t; cvta.to.shared.u64 t, %1; cvt.u32.u64 %0, t; }" : "=r"(a) : "l"(p));
    return a;
}
__device__ __forceinline__ void ldsm4(uint32_t& r0, uint32_t& r1, uint32_t& r2, uint32_t& r3,
                                      uint32_t a) {
    asm volatile("ldmatrix.sync.aligned.m8n8.x4.shared.b16 {%0,%1,%2,%3}, [%4];"
                 : "=r"(r0), "=r"(r1), "=r"(r2), "=r"(r3) : "r"(a));
}
__device__ __forceinline__ void mma16816(float* d, const uint32_t* a, const uint32_t* b) {
    asm volatile(
        "mma.sync.aligned.m16n8k16.row.col.f32.bf16.bf16.f32 "
        "{%0,%1,%2,%3}, {%4,%5,%6,%7}, {%8,%9}, {%0,%1,%2,%3};"
        : "+f"(d[0]), "+f"(d[1]), "+f"(d[2]), "+f"(d[3])
        : "r"(a[0]), "r"(a[1]), "r"(a[2]), "r"(a[3]), "r"(b[0]), "r"(b[1]));
}
__device__ __forceinline__ void cp16(uint32_t dst, const void* src, bool pred) {
    int sz = pred ? 16 : 0;
    asm volatile("cp.async.ca.shared.global [%0], [%1], 16, %2;"
                 :: "r"(dst), "l"(src), "r"(sz) : "memory");
}
#define CP_COMMIT() asm volatile("cp.async.commit_group;" ::: "memory")

// ---------------- edge dtype sniffing + decode -------------------------------
__global__ void detect_kernel(const void* e0, const void* e1, const void* e2, const void* e3) {
    if (threadIdx.x < 4) {
        const void* p = threadIdx.x == 0 ? e0 : threadIdx.x == 1 ? e1 : threadIdx.x == 2 ? e2 : e3;
        const unsigned int* u = (const unsigned int*)p;
        unsigned int acc = 0;
        for (int i = 0; i < 64; i++) acc |= u[2 * i + 1];
        g_is64[threadIdx.x] = (acc == 0) ? 1 : 0;
    }
}

__device__ __forceinline__ int2 load_edge(const void* ep, int is64, int e) {
    int s, d;
    if (is64) {
        const long long* p = (const long long*)ep;
        s = (int)p[e];
        d = (int)p[EE + e];
    } else {
        const int* p = (const int*)ep;
        s = p[e];
        d = p[EE + e];
    }
    return make_int2(s, d);
}

// ---------------- CSR build ---------------------------------------------------
__global__ void zero_counts() {
    int i = blockIdx.x * blockDim.x + threadIdx.x;
    if (i < 4 * NN) { g_deg[i] = 0; g_cursor[i] = 0; }
}

__global__ void build_deg(const void* e0, const void* e1, const void* e2, const void* e3) {
    int e = blockIdx.x * blockDim.x + threadIdx.x;
    int r = blockIdx.y;
    if (e >= EE) return;
    const void* ep = r == 0 ? e0 : r == 1 ? e1 : r == 2 ? e2 : e3;
    int2 sd = load_edge(ep, g_is64[r], e);
    atomicAdd(&g_deg[r * NN + sd.y], 1);
}

__global__ void calc_dinv() {
    int i = blockIdx.x * blockDim.x + threadIdx.x;
    if (i < 4 * NN) g_dinv[i] = rsqrtf((float)g_deg[i] + 1.0f);
}

__global__ void scan_p1() {
    int r = blockIdx.y;
    int i = blockIdx.x * CHUNK + threadIdx.x;
    int v = (i < NN) ? g_deg[r * NN + i] : 0;
    __shared__ int sh[CHUNK];
    sh[threadIdx.x] = v;
    __syncthreads();
    for (int off = CHUNK / 2; off > 0; off >>= 1) {
        if (threadIdx.x < off) sh[threadIdx.x] += sh[threadIdx.x + off];
        __syncthreads();
    }
    if (threadIdx.x == 0) g_chunksum[r * NCHUNK + blockIdx.x] = sh[0];
}

__global__ void scan_p2() {
    int r = blockIdx.x;
    __shared__ int sh[128];
    int v = (threadIdx.x < NCHUNK) ? g_chunksum[r * NCHUNK + threadIdx.x] : 0;
    sh[threadIdx.x] = v;
    __syncthreads();
    for (int off = 1; off < 128; off <<= 1) {
        int t = (threadIdx.x >= off) ? sh[threadIdx.x - off] : 0;
        __syncthreads();
        sh[threadIdx.x] += t;
        __syncthreads();
    }
    if (threadIdx.x < NCHUNK) g_chunkoff[r * NCHUNK + threadIdx.x] = sh[threadIdx.x] - v;
    if (threadIdx.x == 127) g_rowptr[r * (NN + 1) + NN] = sh[127];
}

__global__ void scan_p3() {
    int r = blockIdx.y;
    int i = blockIdx.x * CHUNK + threadIdx.x;
    int v = (i < NN) ? g_deg[r * NN + i] : 0;
    __shared__ int sh[CHUNK];
    sh[threadIdx.x] = v;
    __syncthreads();
    for (int off = 1; off < CHUNK; off <<= 1) {
        int t = (threadIdx.x >= off) ? sh[threadIdx.x - off] : 0;
        __syncthreads();
        sh[threadIdx.x] += t;
        __syncthreads();
    }
    if (i < NN)
        g_rowptr[r * (NN + 1) + i] = g_chunkoff[r * NCHUNK + blockIdx.x] + sh[threadIdx.x] - v;
}

__global__ void build_csr(const void* e0, const void* e1, const void* e2, const void* e3) {
    int e = blockIdx.x * blockDim.x + threadIdx.x;
    int r = blockIdx.y;
    if (e >= EE) return;
    const void* ep = r == 0 ? e0 : r == 1 ? e1 : r == 2 ? e2 : e3;
    int2 sd = load_edge(ep, g_is64[r], e);
    int pos = g_rowptr[r * (NN + 1) + sd.y] + atomicAdd(&g_cursor[r * NN + sd.y], 1);
    g_csr_src[r * EE + pos] = sd.x;
    g_csr_coef[r * EE + pos] = g_dinv[r * NN + sd.x] * g_dinv[r * NN + sd.y];
}

// ---------------- bf16 split conversions --------------------------------------
__global__ void convA(const float* __restrict__ x, __nv_bfloat16* __restrict__ hi,
                      __nv_bfloat16* __restrict__ lo, int n4) {
    int i = blockIdx.x * 256 + threadIdx.x;
    if (i >= n4) return;
    float4 v = ((const float4*)x)[i];
    __nv_bfloat16 h0 = __float2bfloat16(v.x);
    __nv_bfloat16 h1 = __float2bfloat16(v.y);
    __nv_bfloat16 h2 = __float2bfloat16(v.z);
    __nv_bfloat16 h3 = __float2bfloat16(v.w);
    __nv_bfloat162* hp = (__nv_bfloat162*)&hi[i * 4];
    hp[0] = __nv_bfloat162(h0, h1);
    hp[1] = __nv_bfloat162(h2, h3);
    __nv_bfloat162* lp = (__nv_bfloat162*)&lo[i * 4];
    lp[0] = __nv_bfloat162(__float2bfloat16(v.x - __bfloat162float(h0)),
                           __float2bfloat16(v.y - __bfloat162float(h1)));
    lp[1] = __nv_bfloat162(__float2bfloat16(v.z - __bfloat162float(h2)),
                           __float2bfloat16(v.w - __bfloat162float(h3)));
}

// W[k,N] fp32 -> Wt[n,k] bf16 hi/lo (K fixed = 256)
__global__ void convW(const float* __restrict__ W, __nv_bfloat16* __restrict__ hi,
                      __nv_bfloat16* __restrict__ lo, int N) {
    int i = blockIdx.x * 256 + threadIdx.x;
    if (i >= N * 256) return;
    int n = i >> 8, k = i & 255;
    float v = W[k * N + n];
    __nv_bfloat16 h = __float2bfloat16(v);
    hi[i] = h;
    lo[i] = __float2bfloat16(v - __bfloat162float(h));
}

// ---------------- mma.sync GEMM with cp.async 2-stage pipeline ----------------
// block tile 128(M) x 64(N), K chunks of 64 (LDA=72 pad)
#define LDA 72
#define OFF_AHI 0
#define OFF_ALO (128 * LDA)
#define OFF_BHI (2 * 128 * LDA)
#define OFF_BLO (2 * 128 * LDA + 64 * LDA)
#define STG_ELEMS (2 * 128 * LDA + 2 * 64 * LDA)   // 27648 bf16 = 55296 B per stage
#define SMB_TOTAL (2 * STG_ELEMS * 2)              // 110592 B

__global__ void __launch_bounds__(256, 2) gemm_mma(
    const __nv_bfloat16* __restrict__ Ahi, const __nv_bfloat16* __restrict__ Alo,
    const __nv_bfloat16* __restrict__ Bhi, const __nv_bfloat16* __restrict__ Blo,
    float* __restrict__ C, int M, int Ntot,
    const float* __restrict__ bias, const float* __restrict__ P,
    const float* __restrict__ Q, int comb) {
    extern __shared__ __nv_bfloat16 sm[];
    uint32_t sb = smem_u32(sm);
    int tid = threadIdx.x, lane = tid & 31, w = tid >> 5;
    int wm = w & 3, wn = w >> 2;            // 4 warps M x 2 warps N
    int m0 = blockIdx.y * 128, n0 = blockIdx.x * 64;

    float acc[2][4][4];
#pragma unroll
    for (int mi = 0; mi < 2; mi++)
#pragma unroll
        for (int ni = 0; ni < 4; ni++)
#pragma unroll
            for (int q = 0; q < 4; q++) acc[mi][ni][q] = 0.0f;

    // per-thread staging coordinates
    int st_row = tid >> 3;            // 0..31
    int st_col = (tid & 7) * 8;       // element col within 64-chunk
    // ldmatrix source offsets (elements, within stage)
    uint32_t a_off[2], b_off[2];
#pragma unroll
    for (int mi = 0; mi < 2; mi++)
        a_off[mi] = (uint32_t)((wm * 32 + mi * 16 + (lane & 15)) * LDA + (lane >> 4) * 8);
#pragma unroll
    for (int bt = 0; bt < 2; bt++)
        b_off[bt] = (uint32_t)((wn * 32 + bt * 16 + ((lane >> 4) << 3) + (lane & 7)) * LDA +
                               ((lane >> 3) & 1) * 8);

    // stage loader: copy A[128x64] hi/lo + B[64x64] hi/lo for K-chunk k0 into stage buf
    auto issue = [&](int k0, int buf) {
        uint32_t base = sb + (uint32_t)(buf * STG_ELEMS * 2);
#pragma unroll
        for (int i = 0; i < 4; i++) {
            int row = st_row + i * 32;
            bool ok = (m0 + row) < M;
            const __nv_bfloat16* gh = &Ahi[(size_t)(m0 + row) * 256 + k0 + st_col];
            const __nv_bfloat16* gl = &Alo[(size_t)(m0 + row) * 256 + k0 + st_col];
            cp16(base + (uint32_t)((OFF_AHI + row * LDA + st_col) * 2), gh, ok);
            cp16(base + (uint32_t)((OFF_ALO + row * LDA + st_col) * 2), gl, ok);
        }
#pragma unroll
        for (int i = 0; i < 2; i++) {
            int row = st_row + i * 32;
            cp16(base + (uint32_t)((OFF_BHI + row * LDA + st_col) * 2),
                 &Bhi[(size_t)(n0 + row) * 256 + k0 + st_col], true);
            cp16(base + (uint32_t)((OFF_BLO + row * LDA + st_col) * 2),
                 &Blo[(size_t)(n0 + row) * 256 + k0 + st_col], true);
        }
        CP_COMMIT();
    };

    issue(0, 0);

#pragma unroll
    for (int c = 0; c < 4; c++) {
        if (c < 3) issue((c + 1) * 64, (c + 1) & 1);
        if (c < 3) asm volatile("cp.async.wait_group 1;" ::: "memory");
        else       asm volatile("cp.async.wait_group 0;" ::: "memory");
        __syncthreads();
        uint32_t base = sb + (uint32_t)((c & 1) * STG_ELEMS * 2);
#pragma unroll
        for (int ks = 0; ks < 4; ks++) {
            int k = ks * 16;
            uint32_t aH[2][4], aL[2][4], bH[4][2], bL[4][2];
#pragma unroll
            for (int mi = 0; mi < 2; mi++) {
                ldsm4(aH[mi][0], aH[mi][1], aH[mi][2], aH[mi][3],
                      base + ((OFF_AHI + a_off[mi] + k) << 1));
                ldsm4(aL[mi][0], aL[mi][1], aL[mi][2], aL[mi][3],
                      base + ((OFF_ALO + a_off[mi] + k) << 1));
            }
#pragma unroll
            for (int bt = 0; bt < 2; bt++) {
                uint32_t r0, r1, r2, r3;
                ldsm4(r0, r1, r2, r3, base + ((OFF_BHI + b_off[bt] + k) << 1));
                bH[bt * 2][0] = r0; bH[bt * 2][1] = r1;
                bH[bt * 2 + 1][0] = r2; bH[bt * 2 + 1][1] = r3;
                ldsm4(r0, r1, r2, r3, base + ((OFF_BLO + b_off[bt] + k) << 1));
                bL[bt * 2][0] = r0; bL[bt * 2][1] = r1;
                bL[bt * 2 + 1][0] = r2; bL[bt * 2 + 1][1] = r3;
            }
#pragma unroll
            for (int mi = 0; mi < 2; mi++)
#pragma unroll
                for (int ni = 0; ni < 4; ni++) {
                    mma16816(acc[mi][ni], aH[mi], bH[ni]);
                    mma16816(acc[mi][ni], aH[mi], bL[ni]);
                    mma16816(acc[mi][ni], aL[mi], bH[ni]);
                }
        }
        __syncthreads();
    }

    // epilogue
#pragma unroll
    for (int mi = 0; mi < 2; mi++) {
#pragma unroll
        for (int ni = 0; ni < 4; ni++) {
            int col = n0 + wn * 32 + ni * 8 + (lane & 3) * 2;
            int r_lo = m0 + wm * 32 + mi * 16 + (lane >> 2);
            int r_hi = r_lo + 8;
#pragma unroll
            for (int half = 0; half < 2; half++) {
                int row = half ? r_hi : r_lo;
                if (row >= M) continue;
                float2 o;
                o.x = acc[mi][ni][half * 2 + 0];
                o.y = acc[mi][ni][half * 2 + 1];
                size_t base2 = (size_t)row * Ntot + col;
                if (comb) {
                    o.x += bias[col] + 0.5f * (P[base2] + Q[base2]);
                    o.y += bias[col + 1] + 0.5f * (P[base2 + 1] + Q[base2 + 1]);
                }
                *(float2*)&C[base2] = o;
            }
        }
    }
}

// ---------------- GCN aggregation (fused self-loop+bias+lrelu) ----------------
// EMIT16: write bf16 hi/lo split (layer-1); else fp32 out (layer-2)
template <int F, bool EMIT16>
__global__ void agg_kernel(const float* __restrict__ xw, const float* __restrict__ bias,
                           float* __restrict__ out, __nv_bfloat16* __restrict__ ohi,
                           __nv_bfloat16* __restrict__ olo, int r) {
    int v = blockIdx.x;
    int t = threadIdx.x;  // 128 threads
    constexpr int J = F / 128;
    float acc[J];
#pragma unroll
    for (int j = 0; j < J; j++) acc[j] = 0.0f;

    const int* rp = &g_rowptr[r * (NN + 1)];
    const int* cs = &g_csr_src[r * EE];
    const float* cc = &g_csr_coef[r * EE];

    int beg = rp[v], end = rp[v + 1];
    for (int e = beg; e < end; e++) {
        int s = cs[e];
        float c = cc[e];
#pragma unroll
        for (int j = 0; j < J; j++)
            acc[j] += c * __ldg(&xw[s * F + t + j * 128]);
    }
    float dv = g_dinv[r * NN + v];
    float dv2 = dv * dv;
#pragma unroll
    for (int j = 0; j < J; j++) {
        float val = acc[j] + xw[v * F + t + j * 128] * dv2 + bias[t + j * 128];
        val = (val >= 0.0f) ? val : 0.2f * val;
        if (EMIT16) {
            __nv_bfloat16 h = __float2bfloat16(val);
            ohi[(size_t)v * F + t + j * 128] = h;
            olo[(size_t)v * F + t + j * 128] = __float2bfloat16(val - __bfloat162float(h));
        } else {
            out[(size_t)v * F + t + j * 128] = val;
        }
    }
}

// ---------------- launch ------------------------------------------------------
extern "C" void kernel_launch(void* const* d_in, const int* in_sizes, int n_in,
                              void* d_out, int out_size) {
    const float* x[4] = {(const float*)d_in[0], (const float*)d_in[1],
                         (const float*)d_in[2], (const float*)d_in[3]};
    const void* ed[4] = {d_in[4], d_in[5], d_in[6], d_in[7]};
    const float* W1[4] = {(const float*)d_in[8], (const float*)d_in[10],
                          (const float*)d_in[16], (const float*)d_in[18]};
    const float* B1[4] = {(const float*)d_in[9], (const float*)d_in[11],
                          (const float*)d_in[17], (const float*)d_in[19]};
    const float* W2[4] = {(const float*)d_in[12], (const float*)d_in[14],
                          (const float*)d_in[20], (const float*)d_in[22]};
    const float* B2[4] = {(const float*)d_in[13], (const float*)d_in[15],
                          (const float*)d_in[21], (const float*)d_in[23]};
    float* out = (float*)d_out;

    float *xw1, *xw2;
    __nv_bfloat16 *xhi, *xlo, *hhi, *hlo, *whi, *wlo;
    cudaGetSymbolAddress((void**)&xw1, g_xw1);
    cudaGetSymbolAddress((void**)&xw2, g_xw2);
    cudaGetSymbolAddress((void**)&xhi, g_Xhi);
    cudaGetSymbolAddress((void**)&xlo, g_Xlo);
    cudaGetSymbolAddress((void**)&hhi, g_Hhi);
    cudaGetSymbolAddress((void**)&hlo, g_Hlo);
    cudaGetSymbolAddress((void**)&whi, g_Whi);
    cudaGetSymbolAddress((void**)&wlo, g_Wlo);

    cudaFuncSetAttribute(gemm_mma, cudaFuncAttributeMaxDynamicSharedMemorySize, SMB_TOTAL);

    // weight conversion (tiny)
    for (int p = 0; p < 4; p++) {
        convW<<<(256 * 256 + 255) / 256, 256>>>(W1[p], whi + WOFF1(p), wlo + WOFF1(p), 256);
        convW<<<(128 * 256 + 255) / 256, 256>>>(W2[p], whi + WOFF2(p), wlo + WOFF2(p), 128);
    }
    convW<<<(128 * 256 + 255) / 256, 256>>>((const float*)d_in[24], whi + WOFFR(0),
                                            wlo + WOFFR(0), 128);
    convW<<<(128 * 256 + 255) / 256, 256>>>((const float*)d_in[26], whi + WOFFR(1),
                                            wlo + WOFFR(1), 128);

    // CSR build
    detect_kernel<<<1, 32>>>(ed[0], ed[1], ed[2], ed[3]);
    zero_counts<<<(4 * NN + 255) / 256, 256>>>();
    build_deg<<<dim3((EE + 255) / 256, 4), 256>>>(ed[0], ed[1], ed[2], ed[3]);
    calc_dinv<<<(4 * NN + 255) / 256, 256>>>();
    scan_p1<<<dim3(NCHUNK, 4), CHUNK>>>();
    scan_p2<<<4, 128>>>();
    scan_p3<<<dim3(NCHUNK, 4), CHUNK>>>();
    build_csr<<<dim3((EE + 255) / 256, 4), 256>>>(ed[0], ed[1], ed[2], ed[3]);

    const int n4 = NN * 256 / 4;
    dim3 cgrid((n4 + 255) / 256);
    dim3 g1(4, (NN + 127) / 128);   // Ntot=256
    dim3 g2(2, (NN + 127) / 128);   // Ntot=128
    const size_t XSZ = (size_t)NN * 256;

    // convert each input once (x0/x1 reused by residual GEMMs)
    for (int p = 0; p < 4; p++)
        convA<<<cgrid, 256>>>(x[p], xhi + p * XSZ, xlo + p * XSZ, n4);

    for (int p = 0; p < 4; p++) {
        gemm_mma<<<g1, 256, SMB_TOTAL>>>(xhi + p * XSZ, xlo + p * XSZ, whi + WOFF1(p),
                                         wlo + WOFF1(p), xw1, NN, 256,
                                         nullptr, nullptr, nullptr, 0);
        agg_kernel<256, true><<<NN, 128>>>(xw1, B1[p], nullptr, hhi, hlo, p);
        gemm_mma<<<g2, 256, SMB_TOTAL>>>(hhi, hlo, whi + WOFF2(p), wlo + WOFF2(p), xw2, NN, 128,
                                         nullptr, nullptr, nullptr, 0);
        agg_kernel<128, false><<<NN, 128>>>(xw2, B2[p], out + (size_t)(2 + p) * REGSZ,
                                            nullptr, nullptr, p);
    }
    // comb_l = 0.5*(jl+bl) + x_lnc_jac @ W_res_lnc + b_res_lnc
    gemm_mma<<<g2, 256, SMB_TOTAL>>>(xhi, xlo, whi + WOFFR(0), wlo + WOFFR(0), out, NN, 128,
                                     (const float*)d_in[25], out + (size_t)2 * REGSZ,
                                     out + (size_t)4 * REGSZ, 1);
    // comb_p = 0.5*(jp+bp) + x_prot_jac @ W_res_prot + b_res_prot
    gemm_mma<<<g2, 256, SMB_TOTAL>>>(xhi + XSZ, xlo + XSZ, whi + WOFFR(1), wlo + WOFFR(1),
                                     out + (size_t)REGSZ, NN, 128, (const float*)d_in[27],
                                     out + (size_t)3 * REGSZ, out + (size_t)5 * REGSZ, 1);
}

// round 6
// speedup vs baseline: 1.3407x; 1.3407x over previous
#include <cuda_runtime.h>
#include <cuda_bf16.h>
#include <cstdint>

#define NN 50000
#define EE 800000
#define REGSZ (NN * 128)
#define CHUNK 512
#define NCHUNK ((NN + CHUNK - 1) / CHUNK)   // 98

// ---------------- scratch (static device globals; no runtime alloc) ----------
__device__ int   g_deg[4 * NN];
__device__ int   g_cursor[4 * NN];
__device__ int   g_rowptr[4 * (NN + 1)];
__device__ float g_dinv[4 * NN];
__device__ int   g_csr_src[4 * EE];
__device__ float g_csr_coef[4 * EE];
__device__ float g_xw1[NN * 256];
__device__ float g_xw2[NN * 128];
__device__ int   g_is64[4];
__device__ int   g_chunksum[4 * NCHUNK];
__device__ int   g_chunkoff[4 * NCHUNK];
// bf16-split buffers: per-input X (4x), hidden H, weights (transposed [n][k])
__device__ __nv_bfloat16 g_Xhi[4][NN * 256];
__device__ __nv_bfloat16 g_Xlo[4][NN * 256];
__device__ __nv_bfloat16 g_Hhi[NN * 256];
__device__ __nv_bfloat16 g_Hlo[NN * 256];
#define WOFF1(p) ((p) * 65536)
#define WOFF2(p) (262144 + (p) * 32768)
#define WOFFR(i) (393216 + (i) * 32768)
__device__ __nv_bfloat16 g_Whi[458752];
__device__ __nv_bfloat16 g_Wlo[458752];

// ---------------- mma.sync helpers -------------------------------------------
__device__ __forceinline__ uint32_t smem_u32(const void* p) {
    uint32_t a;
    asm("{ .reg .u64 t; cvta.to.shared.u64 t, %1; cvt.u32.u64 %0, t; }" : "=r"(a) : "l"(p));
    return a;
}
__device__ __forceinline__ void ldsm4(uint32_t& r0, uint32_t& r1, uint32_t& r2, uint32_t& r3,
                                      uint32_t a) {
    asm volatile("ldmatrix.sync.aligned.m8n8.x4.shared.b16 {%0,%1,%2,%3}, [%4];"
                 : "=r"(r0), "=r"(r1), "=r"(r2), "=r"(r3) : "r"(a));
}
__device__ __forceinline__ void mma16816(float* d, const uint32_t* a, const uint32_t* b) {
    asm volatile(
        "mma.sync.aligned.m16n8k16.row.col.f32.bf16.bf16.f32 "
        "{%0,%1,%2,%3}, {%4,%5,%6,%7}, {%8,%9}, {%0,%1,%2,%3};"
        : "+f"(d[0]), "+f"(d[1]), "+f"(d[2]), "+f"(d[3])
        : "r"(a[0]), "r"(a[1]), "r"(a[2]), "r"(a[3]), "r"(b[0]), "r"(b[1]));
}

// ---------------- edge dtype sniffing + decode -------------------------------
__global__ void detect_kernel(const void* e0, const void* e1, const void* e2, const void* e3) {
    if (threadIdx.x < 4) {
        const void* p = threadIdx.x == 0 ? e0 : threadIdx.x == 1 ? e1 : threadIdx.x == 2 ? e2 : e3;
        const unsigned int* u = (const unsigned int*)p;
        unsigned int acc = 0;
        for (int i = 0; i < 64; i++) acc |= u[2 * i + 1];
        g_is64[threadIdx.x] = (acc == 0) ? 1 : 0;
    }
}

__device__ __forceinline__ int2 load_edge(const void* ep, int is64, int e) {
    int s, d;
    if (is64) {
        const long long* p = (const long long*)ep;
        s = (int)p[e];
        d = (int)p[EE + e];
    } else {
        const int* p = (const int*)ep;
        s = p[e];
        d = p[EE + e];
    }
    return make_int2(s, d);
}

// ---------------- CSR build ---------------------------------------------------
__global__ void zero_counts() {
    int i = blockIdx.x * blockDim.x + threadIdx.x;
    if (i < 4 * NN) { g_deg[i] = 0; g_cursor[i] = 0; }
}

__global__ void build_deg(const void* e0, const void* e1, const void* e2, const void* e3) {
    int e = blockIdx.x * blockDim.x + threadIdx.x;
    int r = blockIdx.y;
    if (e >= EE) return;
    const void* ep = r == 0 ? e0 : r == 1 ? e1 : r == 2 ? e2 : e3;
    int2 sd = load_edge(ep, g_is64[r], e);
    atomicAdd(&g_deg[r * NN + sd.y], 1);
}

__global__ void calc_dinv() {
    int i = blockIdx.x * blockDim.x + threadIdx.x;
    if (i < 4 * NN) g_dinv[i] = rsqrtf((float)g_deg[i] + 1.0f);
}

__global__ void scan_p1() {
    int r = blockIdx.y;
    int i = blockIdx.x * CHUNK + threadIdx.x;
    int v = (i < NN) ? g_deg[r * NN + i] : 0;
    __shared__ int sh[CHUNK];
    sh[threadIdx.x] = v;
    __syncthreads();
    for (int off = CHUNK / 2; off > 0; off >>= 1) {
        if (threadIdx.x < off) sh[threadIdx.x] += sh[threadIdx.x + off];
        __syncthreads();
    }
    if (threadIdx.x == 0) g_chunksum[r * NCHUNK + blockIdx.x] = sh[0];
}

__global__ void scan_p2() {
    int r = blockIdx.x;
    __shared__ int sh[128];
    int v = (threadIdx.x < NCHUNK) ? g_chunksum[r * NCHUNK + threadIdx.x] : 0;
    sh[threadIdx.x] = v;
    __syncthreads();
    for (int off = 1; off < 128; off <<= 1) {
        int t = (threadIdx.x >= off) ? sh[threadIdx.x - off] : 0;
        __syncthreads();
        sh[threadIdx.x] += t;
        __syncthreads();
    }
    if (threadIdx.x < NCHUNK) g_chunkoff[r * NCHUNK + threadIdx.x] = sh[threadIdx.x] - v;
    if (threadIdx.x == 127) g_rowptr[r * (NN + 1) + NN] = sh[127];
}

__global__ void scan_p3() {
    int r = blockIdx.y;
    int i = blockIdx.x * CHUNK + threadIdx.x;
    int v = (i < NN) ? g_deg[r * NN + i] : 0;
    __shared__ int sh[CHUNK];
    sh[threadIdx.x] = v;
    __syncthreads();
    for (int off = 1; off < CHUNK; off <<= 1) {
        int t = (threadIdx.x >= off) ? sh[threadIdx.x - off] : 0;
        __syncthreads();
        sh[threadIdx.x] += t;
        __syncthreads();
    }
    if (i < NN)
        g_rowptr[r * (NN + 1) + i] = g_chunkoff[r * NCHUNK + blockIdx.x] + sh[threadIdx.x] - v;
}

__global__ void build_csr(const void* e0, const void* e1, const void* e2, const void* e3) {
    int e = blockIdx.x * blockDim.x + threadIdx.x;
    int r = blockIdx.y;
    if (e >= EE) return;
    const void* ep = r == 0 ? e0 : r == 1 ? e1 : r == 2 ? e2 : e3;
    int2 sd = load_edge(ep, g_is64[r], e);
    int pos = g_rowptr[r * (NN + 1) + sd.y] + atomicAdd(&g_cursor[r * NN + sd.y], 1);
    g_csr_src[r * EE + pos] = sd.x;
    g_csr_coef[r * EE + pos] = g_dinv[r * NN + sd.x] * g_dinv[r * NN + sd.y];
}

// ---------------- bf16 split conversions (batched) ----------------------------
// All 4 inputs in one launch: grid.y selects input
__global__ void convA4(const float* __restrict__ x0, const float* __restrict__ x1,
                       const float* __restrict__ x2, const float* __restrict__ x3,
                       __nv_bfloat16* __restrict__ hi, __nv_bfloat16* __restrict__ lo,
                       int n4) {
    int i = blockIdx.x * 256 + threadIdx.x;
    if (i >= n4) return;
    int p = blockIdx.y;
    const float* x = p == 0 ? x0 : p == 1 ? x1 : p == 2 ? x2 : x3;
    size_t off = (size_t)p * NN * 256;
    float4 v = ((const float4*)x)[i];
    __nv_bfloat16 h0 = __float2bfloat16(v.x);
    __nv_bfloat16 h1 = __float2bfloat16(v.y);
    __nv_bfloat16 h2 = __float2bfloat16(v.z);
    __nv_bfloat16 h3 = __float2bfloat16(v.w);
    __nv_bfloat162* hp = (__nv_bfloat162*)&hi[off + (size_t)i * 4];
    hp[0] = __nv_bfloat162(h0, h1);
    hp[1] = __nv_bfloat162(h2, h3);
    __nv_bfloat162* lp = (__nv_bfloat162*)&lo[off + (size_t)i * 4];
    lp[0] = __nv_bfloat162(__float2bfloat16(v.x - __bfloat162float(h0)),
                           __float2bfloat16(v.y - __bfloat162float(h1)));
    lp[1] = __nv_bfloat162(__float2bfloat16(v.z - __bfloat162float(h2)),
                           __float2bfloat16(v.w - __bfloat162float(h3)));
}

// All 10 weight matrices in one launch: grid.y selects matrix
struct WArgs {
    const float* W[10];
    int N[10];
    int off[10];
};
__global__ void convW10(WArgs a, __nv_bfloat16* __restrict__ hi, __nv_bfloat16* __restrict__ lo) {
    int m = blockIdx.y;
    int i = blockIdx.x * 256 + threadIdx.x;
    int N = a.N[m];
    if (i >= N * 256) return;
    int n = i >> 8, k = i & 255;
    float v = a.W[m][k * N + n];
    __nv_bfloat16 h = __float2bfloat16(v);
    hi[a.off[m] + i] = h;
    lo[a.off[m] + i] = __float2bfloat16(v - __bfloat162float(h));
}

// ---------------- mma.sync GEMM: C[M,Ntot] = A @ Wt^T (3-term bf16 split) -----
// block tile 128(M) x 64(N), K streamed in chunks of 64 via smem (LDA=72 pad)
#define LDA 72
#define OFF_AHI 0
#define OFF_ALO (128 * LDA)
#define OFF_BHI (2 * 128 * LDA)
#define OFF_BLO (2 * 128 * LDA + 64 * LDA)
#define SM_ELEMS (2 * 128 * LDA + 2 * 64 * LDA)   // 27648 bf16 = 55296 B

__global__ void __launch_bounds__(256, 2) gemm_mma(
    const __nv_bfloat16* __restrict__ Ahi, const __nv_bfloat16* __restrict__ Alo,
    const __nv_bfloat16* __restrict__ Bhi, const __nv_bfloat16* __restrict__ Blo,
    float* __restrict__ C, int M, int Ntot,
    const float* __restrict__ bias, const float* __restrict__ P,
    const float* __restrict__ Q, int comb) {
    extern __shared__ __nv_bfloat16 sm[];
    uint32_t sb = smem_u32(sm);
    int tid = threadIdx.x, lane = tid & 31, w = tid >> 5;
    int wm = w & 3, wn = w >> 2;            // 4 warps M x 2 warps N
    int m0 = blockIdx.y * 128, n0 = blockIdx.x * 64;

    float acc[2][4][4];
#pragma unroll
    for (int mi = 0; mi < 2; mi++)
#pragma unroll
        for (int ni = 0; ni < 4; ni++)
#pragma unroll
            for (int q = 0; q < 4; q++) acc[mi][ni][q] = 0.0f;

    // ldmatrix source offsets (elements)
    uint32_t a_off[2], b_off[2];
#pragma unroll
    for (int mi = 0; mi < 2; mi++)
        a_off[mi] = (uint32_t)((wm * 32 + mi * 16 + (lane & 15)) * LDA + (lane >> 4) * 8);
#pragma unroll
    for (int bt = 0; bt < 2; bt++)
        b_off[bt] = (uint32_t)((wn * 32 + bt * 16 + ((lane >> 4) << 3) + (lane & 7)) * LDA +
                               ((lane >> 3) & 1) * 8);

    for (int k0 = 0; k0 < 256; k0 += 64) {
        // stage A chunk [128 x 64] hi/lo
#pragma unroll
        for (int i = 0; i < 4; i++) {
            int idx = tid + i * 256;
            int row = idx >> 3, col = (idx & 7) * 8;
            uint4 vh = make_uint4(0, 0, 0, 0), vl = make_uint4(0, 0, 0, 0);
            if (m0 + row < M) {
                vh = *(const uint4*)&Ahi[(size_t)(m0 + row) * 256 + k0 + col];
                vl = *(const uint4*)&Alo[(size_t)(m0 + row) * 256 + k0 + col];
            }
            *(uint4*)&sm[OFF_AHI + row * LDA + col] = vh;
            *(uint4*)&sm[OFF_ALO + row * LDA + col] = vl;
        }
        // stage B chunk [64 x 64] hi/lo
#pragma unroll
        for (int i = 0; i < 2; i++) {
            int idx = tid + i * 256;
            int row = idx >> 3, col = (idx & 7) * 8;
            *(uint4*)&sm[OFF_BHI + row * LDA + col] =
                *(const uint4*)&Bhi[(size_t)(n0 + row) * 256 + k0 + col];
            *(uint4*)&sm[OFF_BLO + row * LDA + col] =
                *(const uint4*)&Blo[(size_t)(n0 + row) * 256 + k0 + col];
        }
        __syncthreads();

#pragma unroll
        for (int ks = 0; ks < 4; ks++) {
            int k = ks * 16;
            uint32_t aH[2][4], aL[2][4], bH[4][2], bL[4][2];
#pragma unroll
            for (int mi = 0; mi < 2; mi++) {
                uint32_t ah = sb + ((OFF_AHI + a_off[mi] + k) << 1);
                uint32_t al = sb + ((OFF_ALO + a_off[mi] + k) << 1);
                ldsm4(aH[mi][0], aH[mi][1], aH[mi][2], aH[mi][3], ah);
                ldsm4(aL[mi][0], aL[mi][1], aL[mi][2], aL[mi][3], al);
            }
#pragma unroll
            for (int bt = 0; bt < 2; bt++) {
                uint32_t bh = sb + ((OFF_BHI + b_off[bt] + k) << 1);
                uint32_t bl = sb + ((OFF_BLO + b_off[bt] + k) << 1);
                uint32_t r0, r1, r2, r3;
                ldsm4(r0, r1, r2, r3, bh);
                bH[bt * 2][0] = r0; bH[bt * 2][1] = r1;
                bH[bt * 2 + 1][0] = r2; bH[bt * 2 + 1][1] = r3;
                ldsm4(r0, r1, r2, r3, bl);
                bL[bt * 2][0] = r0; bL[bt * 2][1] = r1;
                bL[bt * 2 + 1][0] = r2; bL[bt * 2 + 1][1] = r3;
            }
#pragma unroll
            for (int mi = 0; mi < 2; mi++)
#pragma unroll
                for (int ni = 0; ni < 4; ni++) {
                    mma16816(acc[mi][ni], aH[mi], bH[ni]);
                    mma16816(acc[mi][ni], aH[mi], bL[ni]);
                    mma16816(acc[mi][ni], aL[mi], bH[ni]);
                }
        }
        __syncthreads();
    }

    // epilogue
#pragma unroll
    for (int mi = 0; mi < 2; mi++) {
#pragma unroll
        for (int ni = 0; ni < 4; ni++) {
            int col = n0 + wn * 32 + ni * 8 + (lane & 3) * 2;
            int r_lo = m0 + wm * 32 + mi * 16 + (lane >> 2);
            int r_hi = r_lo + 8;
#pragma unroll
            for (int half = 0; half < 2; half++) {
                int row = half ? r_hi : r_lo;
                if (row >= M) continue;
                float2 o;
                o.x = acc[mi][ni][half * 2 + 0];
                o.y = acc[mi][ni][half * 2 + 1];
                size_t base = (size_t)row * Ntot + col;
                if (comb) {
                    o.x += bias[col] + 0.5f * (P[base] + Q[base]);
                    o.y += bias[col + 1] + 0.5f * (P[base + 1] + Q[base + 1]);
                }
                *(float2*)&C[base] = o;
            }
        }
    }
}

// ---------------- GCN aggregation (fused self-loop+bias+lrelu) ----------------
// EMIT16: write bf16 hi/lo split (layer-1); else fp32 out (layer-2)
template <int F, bool EMIT16>
__global__ void agg_kernel(const float* __restrict__ xw, const float* __restrict__ bias,
                           float* __restrict__ out, __nv_bfloat16* __restrict__ ohi,
                           __nv_bfloat16* __restrict__ olo, int r) {
    int v = blockIdx.x;
    int t = threadIdx.x;  // 128 threads
    constexpr int J = F / 128;
    float acc[J];
#pragma unroll
    for (int j = 0; j < J; j++) acc[j] = 0.0f;

    const int* rp = &g_rowptr[r * (NN + 1)];
    const int* cs = &g_csr_src[r * EE];
    const float* cc = &g_csr_coef[r * EE];

    int beg = rp[v], end = rp[v + 1];
    for (int e = beg; e < end; e++) {
        int s = cs[e];
        float c = cc[e];
#pragma unroll
        for (int j = 0; j < J; j++)
            acc[j] += c * __ldg(&xw[s * F + t + j * 128]);
    }
    float dv = g_dinv[r * NN + v];
    float dv2 = dv * dv;
#pragma unroll
    for (int j = 0; j < J; j++) {
        float val = acc[j] + xw[v * F + t + j * 128] * dv2 + bias[t + j * 128];
        val = (val >= 0.0f) ? val : 0.2f * val;
        if (EMIT16) {
            __nv_bfloat16 h = __float2bfloat16(val);
            ohi[(size_t)v * F + t + j * 128] = h;
            olo[(size_t)v * F + t + j * 128] = __float2bfloat16(val - __bfloat162float(h));
        } else {
            out[(size_t)v * F + t + j * 128] = val;
        }
    }
}

// ---------------- launch ------------------------------------------------------
extern "C" void kernel_launch(void* const* d_in, const int* in_sizes, int n_in,
                              void* d_out, int out_size) {
    const float* x[4] = {(const float*)d_in[0], (const float*)d_in[1],
                         (const float*)d_in[2], (const float*)d_in[3]};
    const void* ed[4] = {d_in[4], d_in[5], d_in[6], d_in[7]};
    const float* W1[4] = {(const float*)d_in[8], (const float*)d_in[10],
                          (const float*)d_in[16], (const float*)d_in[18]};
    const float* B1[4] = {(const float*)d_in[9], (const float*)d_in[11],
                          (const float*)d_in[17], (const float*)d_in[19]};
    const float* W2[4] = {(const float*)d_in[12], (const float*)d_in[14],
                          (const float*)d_in[20], (const float*)d_in[22]};
    const float* B2[4] = {(const float*)d_in[13], (const float*)d_in[15],
                          (const float*)d_in[21], (const float*)d_in[23]};
    float* out = (float*)d_out;

    float *xw1, *xw2;
    __nv_bfloat16 *xhi, *xlo, *hhi, *hlo, *whi, *wlo;
    cudaGetSymbolAddress((void**)&xw1, g_xw1);
    cudaGetSymbolAddress((void**)&xw2, g_xw2);
    cudaGetSymbolAddress((void**)&xhi, g_Xhi);
    cudaGetSymbolAddress((void**)&xlo, g_Xlo);
    cudaGetSymbolAddress((void**)&hhi, g_Hhi);
    cudaGetSymbolAddress((void**)&hlo, g_Hlo);
    cudaGetSymbolAddress((void**)&whi, g_Whi);
    cudaGetSymbolAddress((void**)&wlo, g_Wlo);

    const int SMB = SM_ELEMS * 2;
    cudaFuncSetAttribute(gemm_mma, cudaFuncAttributeMaxDynamicSharedMemorySize, SMB);

    // batched weight conversion (one launch for all 10 matrices)
    WArgs wa;
    for (int p = 0; p < 4; p++) {
        wa.W[p] = W1[p];     wa.N[p] = 256;     wa.off[p] = WOFF1(p);
        wa.W[4 + p] = W2[p]; wa.N[4 + p] = 128; wa.off[4 + p] = WOFF2(p);
    }
    wa.W[8] = (const float*)d_in[24]; wa.N[8] = 128; wa.off[8] = WOFFR(0);
    wa.W[9] = (const float*)d_in[26]; wa.N[9] = 128; wa.off[9] = WOFFR(1);
    convW10<<<dim3(256, 10), 256>>>(wa, whi, wlo);

    // CSR build
    detect_kernel<<<1, 32>>>(ed[0], ed[1], ed[2], ed[3]);
    zero_counts<<<(4 * NN + 255) / 256, 256>>>();
    build_deg<<<dim3((EE + 255) / 256, 4), 256>>>(ed[0], ed[1], ed[2], ed[3]);
    calc_dinv<<<(4 * NN + 255) / 256, 256>>>();
    scan_p1<<<dim3(NCHUNK, 4), CHUNK>>>();
    scan_p2<<<4, 128>>>();
    scan_p3<<<dim3(NCHUNK, 4), CHUNK>>>();
    build_csr<<<dim3((EE + 255) / 256, 4), 256>>>(ed[0], ed[1], ed[2], ed[3]);

    const int n4 = NN * 256 / 4;
    // batched input conversion (one launch for all 4 inputs)
    convA4<<<dim3((n4 + 255) / 256, 4), 256>>>(x[0], x[1], x[2], x[3], xhi, xlo, n4);

    dim3 g1(4, (NN + 127) / 128);   // Ntot=256
    dim3 g2(2, (NN + 127) / 128);   // Ntot=128
    const size_t XSZ = (size_t)NN * 256;

    for (int p = 0; p < 4; p++) {
        gemm_mma<<<g1, 256, SMB>>>(xhi + p * XSZ, xlo + p * XSZ, whi + WOFF1(p),
                                   wlo + WOFF1(p), xw1, NN, 256,
                                   nullptr, nullptr, nullptr, 0);
        agg_kernel<256, true><<<NN, 128>>>(xw1, B1[p], nullptr, hhi, hlo, p);
        gemm_mma<<<g2, 256, SMB>>>(hhi, hlo, whi + WOFF2(p), wlo + WOFF2(p), xw2, NN, 128,
                                   nullptr, nullptr, nullptr, 0);
        agg_kernel<128, false><<<NN, 128>>>(xw2, B2[p], out + (size_t)(2 + p) * REGSZ,
                                            nullptr, nullptr, p);
    }
    // comb_l = 0.5*(jl+bl) + x_lnc_jac @ W_res_lnc + b_res_lnc
    gemm_mma<<<g2, 256, SMB>>>(xhi, xlo, whi + WOFFR(0), wlo + WOFFR(0), out, NN, 128,
                               (const float*)d_in[25], out + (size_t)2 * REGSZ,
                               out + (size_t)4 * REGSZ, 1);
    // comb_p = 0.5*(jp+bp) + x_prot_jac @ W_res_prot + b_res_prot
    gemm_mma<<<g2, 256, SMB>>>(xhi + XSZ, xlo + XSZ, whi + WOFFR(1), wlo + WOFFR(1),
                               out + (size_t)REGSZ, NN, 128, (const float*)d_in[27],
                               out + (size_t)3 * REGSZ, out + (size_t)5 * REGSZ, 1);
}

// round 7
// speedup vs baseline: 1.4500x; 1.0815x over previous
#include <cuda_runtime.h>
#include <cuda_bf16.h>
#include <cstdint>

#define NN 50000
#define EE 800000
#define REGSZ (NN * 128)
#define CHUNK 512
#define NCHUNK ((NN + CHUNK - 1) / CHUNK)   // 98

// ---------------- scratch (static device globals; no runtime alloc) ----------
__device__ int   g_deg[4 * NN];
__device__ int   g_cursor[4 * NN];
__device__ int   g_rowptr[4 * (NN + 1)];
__device__ float g_dinv[4 * NN];
__device__ int   g_csr_src[4 * EE];
__device__ float g_csr_coef[4 * EE];
__device__ int   g_is64[4];
__device__ int   g_chunksum[4 * NCHUNK];
__device__ int   g_chunkoff[4 * NCHUNK];
// per-pipeline intermediates (4 concurrent pipelines)
__device__ float g_xw1[4][NN * 256];
__device__ float g_xw2[4][NN * 128];
__device__ __nv_bfloat16 g_Hhi[4][NN * 256];
__device__ __nv_bfloat16 g_Hlo[4][NN * 256];
// bf16-split inputs + weights (transposed [n][k])
__device__ __nv_bfloat16 g_Xhi[4][NN * 256];
__device__ __nv_bfloat16 g_Xlo[4][NN * 256];
#define WOFF1(p) ((p) * 65536)
#define WOFF2(p) (262144 + (p) * 32768)
#define WOFFR(i) (393216 + (i) * 32768)
__device__ __nv_bfloat16 g_Whi[458752];
__device__ __nv_bfloat16 g_Wlo[458752];

// ---------------- mma.sync helpers -------------------------------------------
__device__ __forceinline__ uint32_t smem_u32(const void* p) {
    uint32_t a;
    asm("{ .reg .u64 t; cvta.to.shared.u64 t, %1; cvt.u32.u64 %0, t; }" : "=r"(a) : "l"(p));
    return a;
}
__device__ __forceinline__ void ldsm4(uint32_t& r0, uint32_t& r1, uint32_t& r2, uint32_t& r3,
                                      uint32_t a) {
    asm volatile("ldmatrix.sync.aligned.m8n8.x4.shared.b16 {%0,%1,%2,%3}, [%4];"
                 : "=r"(r0), "=r"(r1), "=r"(r2), "=r"(r3) : "r"(a));
}
__device__ __forceinline__ void mma16816(float* d, const uint32_t* a, const uint32_t* b) {
    asm volatile(
        "mma.sync.aligned.m16n8k16.row.col.f32.bf16.bf16.f32 "
        "{%0,%1,%2,%3}, {%4,%5,%6,%7}, {%8,%9}, {%0,%1,%2,%3};"
        : "+f"(d[0]), "+f"(d[1]), "+f"(d[2]), "+f"(d[3])
        : "r"(a[0]), "r"(a[1]), "r"(a[2]), "r"(a[3]), "r"(b[0]), "r"(b[1]));
}

// ---------------- edge dtype sniffing + decode -------------------------------
__global__ void detect_kernel(const void* e0, const void* e1, const void* e2, const void* e3) {
    if (threadIdx.x < 4) {
        const void* p = threadIdx.x == 0 ? e0 : threadIdx.x == 1 ? e1 : threadIdx.x == 2 ? e2 : e3;
        const unsigned int* u = (const unsigned int*)p;
        unsigned int acc = 0;
        for (int i = 0; i < 64; i++) acc |= u[2 * i + 1];
        g_is64[threadIdx.x] = (acc == 0) ? 1 : 0;
    }
}

__device__ __forceinline__ int2 load_edge(const void* ep, int is64, int e) {
    int s, d;
    if (is64) {
        const long long* p = (const long long*)ep;
        s = (int)p[e];
        d = (int)p[EE + e];
    } else {
        const int* p = (const int*)ep;
        s = p[e];
        d = p[EE + e];
    }
    return make_int2(s, d);
}

// ---------------- CSR build ---------------------------------------------------
__global__ void zero_counts() {
    int i = blockIdx.x * blockDim.x + threadIdx.x;
    if (i < 4 * NN) { g_deg[i] = 0; g_cursor[i] = 0; }
}

__global__ void build_deg(const void* e0, const void* e1, const void* e2, const void* e3) {
    int e = blockIdx.x * blockDim.x + threadIdx.x;
    int r = blockIdx.y;
    if (e >= EE) return;
    const void* ep = r == 0 ? e0 : r == 1 ? e1 : r == 2 ? e2 : e3;
    int2 sd = load_edge(ep, g_is64[r], e);
    atomicAdd(&g_deg[r * NN + sd.y], 1);
}

__global__ void calc_dinv() {
    int i = blockIdx.x * blockDim.x + threadIdx.x;
    if (i < 4 * NN) g_dinv[i] = rsqrtf((float)g_deg[i] + 1.0f);
}

__global__ void scan_p1() {
    int r = blockIdx.y;
    int i = blockIdx.x * CHUNK + threadIdx.x;
    int v = (i < NN) ? g_deg[r * NN + i] : 0;
    __shared__ int sh[CHUNK];
    sh[threadIdx.x] = v;
    __syncthreads();
    for (int off = CHUNK / 2; off > 0; off >>= 1) {
        if (threadIdx.x < off) sh[threadIdx.x] += sh[threadIdx.x + off];
        __syncthreads();
    }
    if (threadIdx.x == 0) g_chunksum[r * NCHUNK + blockIdx.x] = sh[0];
}

__global__ void scan_p2() {
    int r = blockIdx.x;
    __shared__ int sh[128];
    int v = (threadIdx.x < NCHUNK) ? g_chunksum[r * NCHUNK + threadIdx.x] : 0;
    sh[threadIdx.x] = v;
    __syncthreads();
    for (int off = 1; off < 128; off <<= 1) {
        int t = (threadIdx.x >= off) ? sh[threadIdx.x - off] : 0;
        __syncthreads();
        sh[threadIdx.x] += t;
        __syncthreads();
    }
    if (threadIdx.x < NCHUNK) g_chunkoff[r * NCHUNK + threadIdx.x] = sh[threadIdx.x] - v;
    if (threadIdx.x == 127) g_rowptr[r * (NN + 1) + NN] = sh[127];
}

__global__ void scan_p3() {
    int r = blockIdx.y;
    int i = blockIdx.x * CHUNK + threadIdx.x;
    int v = (i < NN) ? g_deg[r * NN + i] : 0;
    __shared__ int sh[CHUNK];
    sh[threadIdx.x] = v;
    __syncthreads();
    for (int off = 1; off < CHUNK; off <<= 1) {
        int t = (threadIdx.x >= off) ? sh[threadIdx.x - off] : 0;
        __syncthreads();
        sh[threadIdx.x] += t;
        __syncthreads();
    }
    if (i < NN)
        g_rowptr[r * (NN + 1) + i] = g_chunkoff[r * NCHUNK + blockIdx.x] + sh[threadIdx.x] - v;
}

__global__ void build_csr(const void* e0, const void* e1, const void* e2, const void* e3) {
    int e = blockIdx.x * blockDim.x + threadIdx.x;
    int r = blockIdx.y;
    if (e >= EE) return;
    const void* ep = r == 0 ? e0 : r == 1 ? e1 : r == 2 ? e2 : e3;
    int2 sd = load_edge(ep, g_is64[r], e);
    int pos = g_rowptr[r * (NN + 1) + sd.y] + atomicAdd(&g_cursor[r * NN + sd.y], 1);
    g_csr_src[r * EE + pos] = sd.x;
    g_csr_coef[r * EE + pos] = g_dinv[r * NN + sd.x] * g_dinv[r * NN + sd.y];
}

// ---------------- bf16 split conversions (batched) ----------------------------
__global__ void convA4(const float* __restrict__ x0, const float* __restrict__ x1,
                       const float* __restrict__ x2, const float* __restrict__ x3,
                       __nv_bfloat16* __restrict__ hi, __nv_bfloat16* __restrict__ lo,
                       int n4) {
    int i = blockIdx.x * 256 + threadIdx.x;
    if (i >= n4) return;
    int p = blockIdx.y;
    const float* x = p == 0 ? x0 : p == 1 ? x1 : p == 2 ? x2 : x3;
    size_t off = (size_t)p * NN * 256;
    float4 v = ((const float4*)x)[i];
    __nv_bfloat16 h0 = __float2bfloat16(v.x);
    __nv_bfloat16 h1 = __float2bfloat16(v.y);
    __nv_bfloat16 h2 = __float2bfloat16(v.z);
    __nv_bfloat16 h3 = __float2bfloat16(v.w);
    __nv_bfloat162* hp = (__nv_bfloat162*)&hi[off + (size_t)i * 4];
    hp[0] = __nv_bfloat162(h0, h1);
    hp[1] = __nv_bfloat162(h2, h3);
    __nv_bfloat162* lp = (__nv_bfloat162*)&lo[off + (size_t)i * 4];
    lp[0] = __nv_bfloat162(__float2bfloat16(v.x - __bfloat162float(h0)),
                           __float2bfloat16(v.y - __bfloat162float(h1)));
    lp[1] = __nv_bfloat162(__float2bfloat16(v.z - __bfloat162float(h2)),
                           __float2bfloat16(v.w - __bfloat162float(h3)));
}

struct WArgs {
    const float* W[10];
    int N[10];
    int off[10];
};
__global__ void convW10(WArgs a, __nv_bfloat16* __restrict__ hi, __nv_bfloat16* __restrict__ lo) {
    int m = blockIdx.y;
    int i = blockIdx.x * 256 + threadIdx.x;
    int N = a.N[m];
    if (i >= N * 256) return;
    int n = i >> 8, k = i & 255;
    float v = a.W[m][k * N + n];
    __nv_bfloat16 h = __float2bfloat16(v);
    hi[a.off[m] + i] = h;
    lo[a.off[m] + i] = __float2bfloat16(v - __bfloat162float(h));
}

// ---------------- mma.sync GEMM: C[M,Ntot] = A @ Wt^T (3-term bf16 split) -----
#define LDA 72
#define OFF_AHI 0
#define OFF_ALO (128 * LDA)
#define OFF_BHI (2 * 128 * LDA)
#define OFF_BLO (2 * 128 * LDA + 64 * LDA)
#define SM_ELEMS (2 * 128 * LDA + 2 * 64 * LDA)   // 27648 bf16 = 55296 B

__global__ void __launch_bounds__(256, 2) gemm_mma(
    const __nv_bfloat16* __restrict__ Ahi, const __nv_bfloat16* __restrict__ Alo,
    const __nv_bfloat16* __restrict__ Bhi, const __nv_bfloat16* __restrict__ Blo,
    float* __restrict__ C, int M, int Ntot,
    const float* __restrict__ bias, const float* __restrict__ P,
    const float* __restrict__ Q, int comb) {
    extern __shared__ __nv_bfloat16 sm[];
    uint32_t sb = smem_u32(sm);
    int tid = threadIdx.x, lane = tid & 31, w = tid >> 5;
    int wm = w & 3, wn = w >> 2;
    int m0 = blockIdx.y * 128, n0 = blockIdx.x * 64;

    float acc[2][4][4];
#pragma unroll
    for (int mi = 0; mi < 2; mi++)
#pragma unroll
        for (int ni = 0; ni < 4; ni++)
#pragma unroll
            for (int q = 0; q < 4; q++) acc[mi][ni][q] = 0.0f;

    uint32_t a_off[2], b_off[2];
#pragma unroll
    for (int mi = 0; mi < 2; mi++)
        a_off[mi] = (uint32_t)((wm * 32 + mi * 16 + (lane & 15)) * LDA + (lane >> 4) * 8);
#pragma unroll
    for (int bt = 0; bt < 2; bt++)
        b_off[bt] = (uint32_t)((wn * 32 + bt * 16 + ((lane >> 4) << 3) + (lane & 7)) * LDA +
                               ((lane >> 3) & 1) * 8);

    for (int k0 = 0; k0 < 256; k0 += 64) {
#pragma unroll
        for (int i = 0; i < 4; i++) {
            int idx = tid + i * 256;
            int row = idx >> 3, col = (idx & 7) * 8;
            uint4 vh = make_uint4(0, 0, 0, 0), vl = make_uint4(0, 0, 0, 0);
            if (m0 + row < M) {
                vh = *(const uint4*)&Ahi[(size_t)(m0 + row) * 256 + k0 + col];
                vl = *(const uint4*)&Alo[(size_t)(m0 + row) * 256 + k0 + col];
            }
            *(uint4*)&sm[OFF_AHI + row * LDA + col] = vh;
            *(uint4*)&sm[OFF_ALO + row * LDA + col] = vl;
        }
#pragma unroll
        for (int i = 0; i < 2; i++) {
            int idx = tid + i * 256;
            int row = idx >> 3, col = (idx & 7) * 8;
            *(uint4*)&sm[OFF_BHI + row * LDA + col] =
                *(const uint4*)&Bhi[(size_t)(n0 + row) * 256 + k0 + col];
            *(uint4*)&sm[OFF_BLO + row * LDA + col] =
                *(const uint4*)&Blo[(size_t)(n0 + row) * 256 + k0 + col];
        }
        __syncthreads();

#pragma unroll
        for (int ks = 0; ks < 4; ks++) {
            int k = ks * 16;
            uint32_t aH[2][4], aL[2][4], bH[4][2], bL[4][2];
#pragma unroll
            for (int mi = 0; mi < 2; mi++) {
                ldsm4(aH[mi][0], aH[mi][1], aH[mi][2], aH[mi][3],
                      sb + ((OFF_AHI + a_off[mi] + k) << 1));
                ldsm4(aL[mi][0], aL[mi][1], aL[mi][2], aL[mi][3],
                      sb + ((OFF_ALO + a_off[mi] + k) << 1));
            }
#pragma unroll
            for (int bt = 0; bt < 2; bt++) {
                uint32_t r0, r1, r2, r3;
                ldsm4(r0, r1, r2, r3, sb + ((OFF_BHI + b_off[bt] + k) << 1));
                bH[bt * 2][0] = r0; bH[bt * 2][1] = r1;
                bH[bt * 2 + 1][0] = r2; bH[bt * 2 + 1][1] = r3;
                ldsm4(r0, r1, r2, r3, sb + ((OFF_BLO + b_off[bt] + k) << 1));
                bL[bt * 2][0] = r0; bL[bt * 2][1] = r1;
                bL[bt * 2 + 1][0] = r2; bL[bt * 2 + 1][1] = r3;
            }
#pragma unroll
            for (int mi = 0; mi < 2; mi++)
#pragma unroll
                for (int ni = 0; ni < 4; ni++) {
                    mma16816(acc[mi][ni], aH[mi], bH[ni]);
                    mma16816(acc[mi][ni], aH[mi], bL[ni]);
                    mma16816(acc[mi][ni], aL[mi], bH[ni]);
                }
        }
        __syncthreads();
    }

#pragma unroll
    for (int mi = 0; mi < 2; mi++) {
#pragma unroll
        for (int ni = 0; ni < 4; ni++) {
            int col = n0 + wn * 32 + ni * 8 + (lane & 3) * 2;
            int r_lo = m0 + wm * 32 + mi * 16 + (lane >> 2);
            int r_hi = r_lo + 8;
#pragma unroll
            for (int half = 0; half < 2; half++) {
                int row = half ? r_hi : r_lo;
                if (row >= M) continue;
                float2 o;
                o.x = acc[mi][ni][half * 2 + 0];
                o.y = acc[mi][ni][half * 2 + 1];
                size_t base = (size_t)row * Ntot + col;
                if (comb) {
                    o.x += bias[col] + 0.5f * (P[base] + Q[base]);
                    o.y += bias[col + 1] + 0.5f * (P[base + 1] + Q[base + 1]);
                }
                *(float2*)&C[base] = o;
            }
        }
    }
}

// ---------------- GCN aggregation (fused self-loop+bias+lrelu) ----------------
template <int F, bool EMIT16>
__global__ void agg_kernel(const float* __restrict__ xw, const float* __restrict__ bias,
                           float* __restrict__ out, __nv_bfloat16* __restrict__ ohi,
                           __nv_bfloat16* __restrict__ olo, int r) {
    int v = blockIdx.x;
    int t = threadIdx.x;  // 128 threads
    constexpr int J = F / 128;
    float acc[J];
#pragma unroll
    for (int j = 0; j < J; j++) acc[j] = 0.0f;

    const int* rp = &g_rowptr[r * (NN + 1)];
    const int* cs = &g_csr_src[r * EE];
    const float* cc = &g_csr_coef[r * EE];

    int beg = rp[v], end = rp[v + 1];
    for (int e = beg; e < end; e++) {
        int s = cs[e];
        float c = cc[e];
#pragma unroll
        for (int j = 0; j < J; j++)
            acc[j] += c * __ldg(&xw[s * F + t + j * 128]);
    }
    float dv = g_dinv[r * NN + v];
    float dv2 = dv * dv;
#pragma unroll
    for (int j = 0; j < J; j++) {
        float val = acc[j] + xw[v * F + t + j * 128] * dv2 + bias[t + j * 128];
        val = (val >= 0.0f) ? val : 0.2f * val;
        if (EMIT16) {
            __nv_bfloat16 h = __float2bfloat16(val);
            ohi[(size_t)v * F + t + j * 128] = h;
            olo[(size_t)v * F + t + j * 128] = __float2bfloat16(val - __bfloat162float(h));
        } else {
            out[(size_t)v * F + t + j * 128] = val;
        }
    }
}

// ---------------- launch ------------------------------------------------------
extern "C" void kernel_launch(void* const* d_in, const int* in_sizes, int n_in,
                              void* d_out, int out_size) {
    const float* x[4] = {(const float*)d_in[0], (const float*)d_in[1],
                         (const float*)d_in[2], (const float*)d_in[3]};
    const void* ed[4] = {d_in[4], d_in[5], d_in[6], d_in[7]};
    const float* W1[4] = {(const float*)d_in[8], (const float*)d_in[10],
                          (const float*)d_in[16], (const float*)d_in[18]};
    const float* B1[4] = {(const float*)d_in[9], (const float*)d_in[11],
                          (const float*)d_in[17], (const float*)d_in[19]};
    const float* W2[4] = {(const float*)d_in[12], (const float*)d_in[14],
                          (const float*)d_in[20], (const float*)d_in[22]};
    const float* B2[4] = {(const float*)d_in[13], (const float*)d_in[15],
                          (const float*)d_in[21], (const float*)d_in[23]};
    float* out = (float*)d_out;

    float *xw1b, *xw2b;
    __nv_bfloat16 *xhi, *xlo, *hhib, *hlob, *whi, *wlo;
    cudaGetSymbolAddress((void**)&xw1b, g_xw1);
    cudaGetSymbolAddress((void**)&xw2b, g_xw2);
    cudaGetSymbolAddress((void**)&xhi, g_Xhi);
    cudaGetSymbolAddress((void**)&xlo, g_Xlo);
    cudaGetSymbolAddress((void**)&hhib, g_Hhi);
    cudaGetSymbolAddress((void**)&hlob, g_Hlo);
    cudaGetSymbolAddress((void**)&whi, g_Whi);
    cudaGetSymbolAddress((void**)&wlo, g_Wlo);

    const int SMB = SM_ELEMS * 2;
    cudaFuncSetAttribute(gemm_mma, cudaFuncAttributeMaxDynamicSharedMemorySize, SMB);

    // streams/events created once, before the capture call
    static cudaStream_t s1 = nullptr, s2 = nullptr, s3 = nullptr;
    static cudaEvent_t evRoot = nullptr, evConv = nullptr, evCSR = nullptr;
    static cudaEvent_t evS2 = nullptr, evS3 = nullptr, evS1J = nullptr;
    if (!s1) {
        cudaStreamCreateWithFlags(&s1, cudaStreamNonBlocking);
        cudaStreamCreateWithFlags(&s2, cudaStreamNonBlocking);
        cudaStreamCreateWithFlags(&s3, cudaStreamNonBlocking);
        cudaEventCreateWithFlags(&evRoot, cudaEventDisableTiming);
        cudaEventCreateWithFlags(&evConv, cudaEventDisableTiming);
        cudaEventCreateWithFlags(&evCSR, cudaEventDisableTiming);
        cudaEventCreateWithFlags(&evS2, cudaEventDisableTiming);
        cudaEventCreateWithFlags(&evS3, cudaEventDisableTiming);
        cudaEventCreateWithFlags(&evS1J, cudaEventDisableTiming);
    }

    // ---- fork: CSR build on s3, conversions on origin ----
    cudaEventRecord(evRoot, 0);
    cudaStreamWaitEvent(s3, evRoot, 0);

    detect_kernel<<<1, 32, 0, s3>>>(ed[0], ed[1], ed[2], ed[3]);
    zero_counts<<<(4 * NN + 255) / 256, 256, 0, s3>>>();
    build_deg<<<dim3((EE + 255) / 256, 4), 256, 0, s3>>>(ed[0], ed[1], ed[2], ed[3]);
    calc_dinv<<<(4 * NN + 255) / 256, 256, 0, s3>>>();
    scan_p1<<<dim3(NCHUNK, 4), CHUNK, 0, s3>>>();
    scan_p2<<<4, 128, 0, s3>>>();
    scan_p3<<<dim3(NCHUNK, 4), CHUNK, 0, s3>>>();
    build_csr<<<dim3((EE + 255) / 256, 4), 256, 0, s3>>>(ed[0], ed[1], ed[2], ed[3]);
    cudaEventRecord(evCSR, s3);

    WArgs wa;
    for (int p = 0; p < 4; p++) {
        wa.W[p] = W1[p];     wa.N[p] = 256;     wa.off[p] = WOFF1(p);
        wa.W[4 + p] = W2[p]; wa.N[4 + p] = 128; wa.off[4 + p] = WOFF2(p);
    }
    wa.W[8] = (const float*)d_in[24]; wa.N[8] = 128; wa.off[8] = WOFFR(0);
    wa.W[9] = (const float*)d_in[26]; wa.N[9] = 128; wa.off[9] = WOFFR(1);
    convW10<<<dim3(256, 10), 256>>>(wa, whi, wlo);

    const int n4 = NN * 256 / 4;
    convA4<<<dim3((n4 + 255) / 256, 4), 256>>>(x[0], x[1], x[2], x[3], xhi, xlo, n4);
    cudaEventRecord(evConv, 0);
    cudaStreamWaitEvent(s1, evConv, 0);
    cudaStreamWaitEvent(s2, evConv, 0);
    cudaStreamWaitEvent(s3, evConv, 0);

    dim3 g1(4, (NN + 127) / 128);   // Ntot=256
    dim3 g2(2, (NN + 127) / 128);   // Ntot=128
    const size_t XSZ = (size_t)NN * 256;
    const size_t X2SZ = (size_t)NN * 128;

    cudaStream_t ps[4] = {(cudaStream_t)0, s1, s2, s3};
    for (int p = 0; p < 4; p++) {
        cudaStream_t st = ps[p];
        float* xw1 = xw1b + p * XSZ;
        float* xw2 = xw2b + p * X2SZ;
        __nv_bfloat16* hhi = hhib + p * XSZ;
        __nv_bfloat16* hlo = hlob + p * XSZ;

        gemm_mma<<<g1, 256, SMB, st>>>(xhi + p * XSZ, xlo + p * XSZ, whi + WOFF1(p),
                                       wlo + WOFF1(p), xw1, NN, 256,
                                       nullptr, nullptr, nullptr, 0);
        if (p != 3) cudaStreamWaitEvent(st, evCSR, 0);  // s3 already ordered after CSR
        agg_kernel<256, true><<<NN, 128, 0, st>>>(xw1, B1[p], nullptr, hhi, hlo, p);
        gemm_mma<<<g2, 256, SMB, st>>>(hhi, hlo, whi + WOFF2(p), wlo + WOFF2(p), xw2, NN, 128,
                                       nullptr, nullptr, nullptr, 0);
        agg_kernel<128, false><<<NN, 128, 0, st>>>(xw2, B2[p], out + (size_t)(2 + p) * REGSZ,
                                                   nullptr, nullptr, p);
    }

    // ---- join + residual/combine GEMMs ----
    // comb_l needs pipelines 0 (origin) and 2 (s2)
    cudaEventRecord(evS2, s2);
    cudaStreamWaitEvent(0, evS2, 0);
    gemm_mma<<<g2, 256, SMB>>>(xhi, xlo, whi + WOFFR(0), wlo + WOFFR(0), out, NN, 128,
                               (const float*)d_in[25], out + (size_t)2 * REGSZ,
                               out + (size_t)4 * REGSZ, 1);
    // comb_p needs pipelines 1 (s1) and 3 (s3); run on s1
    cudaEventRecord(evS3, s3);
    cudaStreamWaitEvent(s1, evS3, 0);
    gemm_mma<<<g2, 256, SMB, s1>>>(xhi + XSZ, xlo + XSZ, whi + WOFFR(1), wlo + WOFFR(1),
                                   out + (size_t)REGSZ, NN, 128, (const float*)d_in[27],
                                   out + (size_t)3 * REGSZ, out + (size_t)5 * REGSZ, 1);
    cudaEventRecord(evS1J, s1);
    cudaStreamWaitEvent(0, evS1J, 0);
}

// round 8
// speedup vs baseline: 1.4927x; 1.0294x over previous
#include <cuda_runtime.h>
#include <cuda_bf16.h>
#include <cstdint>

#define NN 50000
#define EE 800000
#define REGSZ (NN * 128)
#define CHUNK 512
#define NCHUNK ((NN + CHUNK - 1) / CHUNK)   // 98

// ---------------- scratch (static device globals; no runtime alloc) ----------
__device__ int   g_deg[4 * NN];
__device__ int   g_cursor[4 * NN];
__device__ int   g_rowptr[4 * (NN + 1)];
__device__ float g_dinv[4 * NN];
__device__ int   g_csr_src[4 * EE];
__device__ float g_csr_coef[4 * EE];
__device__ int   g_is64[4];
__device__ int   g_chunksum[4 * NCHUNK];
__device__ int   g_chunkoff[4 * NCHUNK];
// per-pipeline intermediates (4 concurrent pipelines)
__device__ float g_xw1[4][NN * 256];
__device__ float g_xw2[4][NN * 128];
__device__ __nv_bfloat16 g_Hhi[4][NN * 256];
__device__ __nv_bfloat16 g_Hlo[4][NN * 256];
// bf16-split inputs + weights (transposed [n][k])
__device__ __nv_bfloat16 g_Xhi[4][NN * 256];
__device__ __nv_bfloat16 g_Xlo[4][NN * 256];
#define WOFF1(p) ((p) * 65536)
#define WOFF2(p) (262144 + (p) * 32768)
#define WOFFR(i) (393216 + (i) * 32768)
__device__ __nv_bfloat16 g_Whi[458752];
__device__ __nv_bfloat16 g_Wlo[458752];

// ---------------- mma.sync / cp.async helpers --------------------------------
__device__ __forceinline__ uint32_t smem_u32(const void* p) {
    uint32_t a;
    asm("{ .reg .u64 t; cvta.to.shared.u64 t, %1; cvt.u32.u64 %0, t; }" : "=r"(a) : "l"(p));
    return a;
}
__device__ __forceinline__ void ldsm4(uint32_t& r0, uint32_t& r1, uint32_t& r2, uint32_t& r3,
                                      uint32_t a) {
    asm volatile("ldmatrix.sync.aligned.m8n8.x4.shared.b16 {%0,%1,%2,%3}, [%4];"
                 : "=r"(r0), "=r"(r1), "=r"(r2), "=r"(r3) : "r"(a));
}
__device__ __forceinline__ void mma16816(float* d, const uint32_t* a, const uint32_t* b) {
    asm volatile(
        "mma.sync.aligned.m16n8k16.row.col.f32.bf16.bf16.f32 "
        "{%0,%1,%2,%3}, {%4,%5,%6,%7}, {%8,%9}, {%0,%1,%2,%3};"
        : "+f"(d[0]), "+f"(d[1]), "+f"(d[2]), "+f"(d[3])
        : "r"(a[0]), "r"(a[1]), "r"(a[2]), "r"(a[3]), "r"(b[0]), "r"(b[1]));
}
__device__ __forceinline__ void cp16(uint32_t dst, const void* src, bool pred) {
    int sz = pred ? 16 : 0;
    asm volatile("cp.async.ca.shared.global [%0], [%1], 16, %2;"
                 :: "r"(dst), "l"(src), "r"(sz) : "memory");
}
#define CP_COMMIT() asm volatile("cp.async.commit_group;" ::: "memory")

// ---------------- edge dtype sniffing + decode -------------------------------
__global__ void detect_kernel(const void* e0, const void* e1, const void* e2, const void* e3) {
    if (threadIdx.x < 4) {
        const void* p = threadIdx.x == 0 ? e0 : threadIdx.x == 1 ? e1 : threadIdx.x == 2 ? e2 : e3;
        const unsigned int* u = (const unsigned int*)p;
        unsigned int acc = 0;
        for (int i = 0; i < 64; i++) acc |= u[2 * i + 1];
        g_is64[threadIdx.x] = (acc == 0) ? 1 : 0;
    }
}

__device__ __forceinline__ int2 load_edge(const void* ep, int is64, int e) {
    int s, d;
    if (is64) {
        const long long* p = (const long long*)ep;
        s = (int)p[e];
        d = (int)p[EE + e];
    } else {
        const int* p = (const int*)ep;
        s = p[e];
        d = p[EE + e];
    }
    return make_int2(s, d);
}

// ---------------- CSR build ---------------------------------------------------
__global__ void zero_counts() {
    int i = blockIdx.x * blockDim.x + threadIdx.x;
    if (i < 4 * NN) { g_deg[i] = 0; g_cursor[i] = 0; }
}

__global__ void build_deg(const void* e0, const void* e1, const void* e2, const void* e3) {
    int e = blockIdx.x * blockDim.x + threadIdx.x;
    int r = blockIdx.y;
    if (e >= EE) return;
    const void* ep = r == 0 ? e0 : r == 1 ? e1 : r == 2 ? e2 : e3;
    int2 sd = load_edge(ep, g_is64[r], e);
    atomicAdd(&g_deg[r * NN + sd.y], 1);
}

__global__ void calc_dinv() {
    int i = blockIdx.x * blockDim.x + threadIdx.x;
    if (i < 4 * NN) g_dinv[i] = rsqrtf((float)g_deg[i] + 1.0f);
}

__global__ void scan_p1() {
    int r = blockIdx.y;
    int i = blockIdx.x * CHUNK + threadIdx.x;
    int v = (i < NN) ? g_deg[r * NN + i] : 0;
    __shared__ int sh[CHUNK];
    sh[threadIdx.x] = v;
    __syncthreads();
    for (int off = CHUNK / 2; off > 0; off >>= 1) {
        if (threadIdx.x < off) sh[threadIdx.x] += sh[threadIdx.x + off];
        __syncthreads();
    }
    if (threadIdx.x == 0) g_chunksum[r * NCHUNK + blockIdx.x] = sh[0];
}

__global__ void scan_p2() {
    int r = blockIdx.x;
    __shared__ int sh[128];
    int v = (threadIdx.x < NCHUNK) ? g_chunksum[r * NCHUNK + threadIdx.x] : 0;
    sh[threadIdx.x] = v;
    __syncthreads();
    for (int off = 1; off < 128; off <<= 1) {
        int t = (threadIdx.x >= off) ? sh[threadIdx.x - off] : 0;
        __syncthreads();
        sh[threadIdx.x] += t;
        __syncthreads();
    }
    if (threadIdx.x < NCHUNK) g_chunkoff[r * NCHUNK + threadIdx.x] = sh[threadIdx.x] - v;
    if (threadIdx.x == 127) g_rowptr[r * (NN + 1) + NN] = sh[127];
}

__global__ void scan_p3() {
    int r = blockIdx.y;
    int i = blockIdx.x * CHUNK + threadIdx.x;
    int v = (i < NN) ? g_deg[r * NN + i] : 0;
    __shared__ int sh[CHUNK];
    sh[threadIdx.x] = v;
    __syncthreads();
    for (int off = 1; off < CHUNK; off <<= 1) {
        int t = (threadIdx.x >= off) ? sh[threadIdx.x - off] : 0;
        __syncthreads();
        sh[threadIdx.x] += t;
        __syncthreads();
    }
    if (i < NN)
        g_rowptr[r * (NN + 1) + i] = g_chunkoff[r * NCHUNK + blockIdx.x] + sh[threadIdx.x] - v;
}

__global__ void build_csr(const void* e0, const void* e1, const void* e2, const void* e3) {
    int e = blockIdx.x * blockDim.x + threadIdx.x;
    int r = blockIdx.y;
    if (e >= EE) return;
    const void* ep = r == 0 ? e0 : r == 1 ? e1 : r == 2 ? e2 : e3;
    int2 sd = load_edge(ep, g_is64[r], e);
    int pos = g_rowptr[r * (NN + 1) + sd.y] + atomicAdd(&g_cursor[r * NN + sd.y], 1);
    g_csr_src[r * EE + pos] = sd.x;
    g_csr_coef[r * EE + pos] = g_dinv[r * NN + sd.x] * g_dinv[r * NN + sd.y];
}

// ---------------- bf16 split conversions (batched) ----------------------------
__global__ void convA4(const float* __restrict__ x0, const float* __restrict__ x1,
                       const float* __restrict__ x2, const float* __restrict__ x3,
                       __nv_bfloat16* __restrict__ hi, __nv_bfloat16* __restrict__ lo,
                       int n4) {
    int i = blockIdx.x * 256 + threadIdx.x;
    if (i >= n4) return;
    int p = blockIdx.y;
    const float* x = p == 0 ? x0 : p == 1 ? x1 : p == 2 ? x2 : x3;
    size_t off = (size_t)p * NN * 256;
    float4 v = ((const float4*)x)[i];
    __nv_bfloat16 h0 = __float2bfloat16(v.x);
    __nv_bfloat16 h1 = __float2bfloat16(v.y);
    __nv_bfloat16 h2 = __float2bfloat16(v.z);
    __nv_bfloat16 h3 = __float2bfloat16(v.w);
    __nv_bfloat162* hp = (__nv_bfloat162*)&hi[off + (size_t)i * 4];
    hp[0] = __nv_bfloat162(h0, h1);
    hp[1] = __nv_bfloat162(h2, h3);
    __nv_bfloat162* lp = (__nv_bfloat162*)&lo[off + (size_t)i * 4];
    lp[0] = __nv_bfloat162(__float2bfloat16(v.x - __bfloat162float(h0)),
                           __float2bfloat16(v.y - __bfloat162float(h1)));
    lp[1] = __nv_bfloat162(__float2bfloat16(v.z - __bfloat162float(h2)),
                           __float2bfloat16(v.w - __bfloat162float(h3)));
}

struct WArgs {
    const float* W[10];
    int N[10];
    int off[10];
};
__global__ void convW10(WArgs a, __nv_bfloat16* __restrict__ hi, __nv_bfloat16* __restrict__ lo) {
    int m = blockIdx.y;
    int i = blockIdx.x * 256 + threadIdx.x;
    int N = a.N[m];
    if (i >= N * 256) return;
    int n = i >> 8, k = i & 255;
    float v = a.W[m][k * N + n];
    __nv_bfloat16 h = __float2bfloat16(v);
    hi[a.off[m] + i] = h;
    lo[a.off[m] + i] = __float2bfloat16(v - __bfloat162float(h));
}

// ---------------- mma.sync GEMM, 3-stage cp.async K32 pipeline ---------------
// block tile 128(M) x 64(N); K=256 in 8 chunks of 32 (LDA=40 pad, conflict-free)
#define KC 32
#define LDA 40
#define S_AHI 0
#define S_ALO (128 * LDA)
#define S_BHI (2 * 128 * LDA)
#define S_BLO (2 * 128 * LDA + 64 * LDA)
#define STG_E (2 * 128 * LDA + 2 * 64 * LDA)   // 15360 elems = 30720 B/stage
#define NSTG 3
#define SMB_GEMM (NSTG * STG_E * 2)            // 92160 B

__global__ void __launch_bounds__(256, 2) gemm_mma(
    const __nv_bfloat16* __restrict__ Ahi, const __nv_bfloat16* __restrict__ Alo,
    const __nv_bfloat16* __restrict__ Bhi, const __nv_bfloat16* __restrict__ Blo,
    float* __restrict__ C, int M, int Ntot,
    const float* __restrict__ bias, const float* __restrict__ P,
    const float* __restrict__ Q, int comb) {
    extern __shared__ __nv_bfloat16 sm[];
    uint32_t sb = smem_u32(sm);
    int tid = threadIdx.x, lane = tid & 31, w = tid >> 5;
    int wm = w & 3, wn = w >> 2;
    int m0 = blockIdx.y * 128, n0 = blockIdx.x * 64;

    float acc[2][4][4];
#pragma unroll
    for (int mi = 0; mi < 2; mi++)
#pragma unroll
        for (int ni = 0; ni < 4; ni++)
#pragma unroll
            for (int q = 0; q < 4; q++) acc[mi][ni][q] = 0.0f;

    // staging coords: 16B per thread, 4 col-groups x 64 rows per 256 threads
    int st_row = tid >> 2;           // 0..63
    int st_col = (tid & 3) * 8;      // 0,8,16,24

    // ldmatrix fragment offsets (elements, within a stage)
    uint32_t a_off[2], b_off[2];
#pragma unroll
    for (int mi = 0; mi < 2; mi++)
        a_off[mi] = (uint32_t)((wm * 32 + mi * 16 + (lane & 15)) * LDA + (lane >> 4) * 8);
#pragma unroll
    for (int bt = 0; bt < 2; bt++)
        b_off[bt] = (uint32_t)((wn * 32 + bt * 16 + ((lane >> 4) << 3) + (lane & 7)) * LDA +
                               ((lane >> 3) & 1) * 8);

    auto issue = [&](int c) {
        int k0 = c * KC;
        uint32_t base = sb + (uint32_t)((c % NSTG) * STG_E * 2);
#pragma unroll
        for (int i = 0; i < 2; i++) {
            int row = st_row + i * 64;
            int gr = m0 + row;
            bool ok = gr < M;
            int grc = ok ? gr : (M - 1);
            cp16(base + (uint32_t)((S_AHI + row * LDA + st_col) * 2),
                 &Ahi[(size_t)grc * 256 + k0 + st_col], ok);
            cp16(base + (uint32_t)((S_ALO + row * LDA + st_col) * 2),
                 &Alo[(size_t)grc * 256 + k0 + st_col], ok);
        }
        cp16(base + (uint32_t)((S_BHI + st_row * LDA + st_col) * 2),
             &Bhi[(size_t)(n0 + st_row) * 256 + k0 + st_col], true);
        cp16(base + (uint32_t)((S_BLO + st_row * LDA + st_col) * 2),
             &Blo[(size_t)(n0 + st_row) * 256 + k0 + st_col], true);
        CP_COMMIT();
    };

    issue(0);
    issue(1);

#pragma unroll
    for (int c = 0; c < 8; c++) {
        if (c < 7) asm volatile("cp.async.wait_group 1;" ::: "memory");
        else       asm volatile("cp.async.wait_group 0;" ::: "memory");
        __syncthreads();
        if (c + 2 < 8) issue(c + 2);

        uint32_t base = sb + (uint32_t)((c % NSTG) * STG_E * 2);
#pragma unroll
        for (int ks = 0; ks < 2; ks++) {
            int k = ks * 16;
            uint32_t aH[2][4], aL[2][4], bH[4][2], bL[4][2];
#pragma unroll
            for (int mi = 0; mi < 2; mi++) {
                ldsm4(aH[mi][0], aH[mi][1], aH[mi][2], aH[mi][3],
                      base + ((S_AHI + a_off[mi] + k) << 1));
                ldsm4(aL[mi][0], aL[mi][1], aL[mi][2], aL[mi][3],
                      base + ((S_ALO + a_off[mi] + k) << 1));
            }
#pragma unroll
            for (int bt = 0; bt < 2; bt++) {
                uint32_t r0, r1, r2, r3;
                ldsm4(r0, r1, r2, r3, base + ((S_BHI + b_off[bt] + k) << 1));
                bH[bt * 2][0] = r0; bH[bt * 2][1] = r1;
                bH[bt * 2 + 1][0] = r2; bH[bt * 2 + 1][1] = r3;
                ldsm4(r0, r1, r2, r3, base + ((S_BLO + b_off[bt] + k) << 1));
                bL[bt * 2][0] = r0; bL[bt * 2][1] = r1;
                bL[bt * 2 + 1][0] = r2; bL[bt * 2 + 1][1] = r3;
            }
#pragma unroll
            for (int mi = 0; mi < 2; mi++)
#pragma unroll
                for (int ni = 0; ni < 4; ni++) {
                    mma16816(acc[mi][ni], aH[mi], bH[ni]);
                    mma16816(acc[mi][ni], aH[mi], bL[ni]);
                    mma16816(acc[mi][ni], aL[mi], bH[ni]);
                }
        }
    }

    // epilogue
#pragma unroll
    for (int mi = 0; mi < 2; mi++) {
#pragma unroll
        for (int ni = 0; ni < 4; ni++) {
            int col = n0 + wn * 32 + ni * 8 + (lane & 3) * 2;
            int r_lo = m0 + wm * 32 + mi * 16 + (lane >> 2);
            int r_hi = r_lo + 8;
#pragma unroll
            for (int half = 0; half < 2; half++) {
                int row = half ? r_hi : r_lo;
                if (row >= M) continue;
                float2 o;
                o.x = acc[mi][ni][half * 2 + 0];
                o.y = acc[mi][ni][half * 2 + 1];
                size_t base = (size_t)row * Ntot + col;
                if (comb) {
                    o.x += bias[col] + 0.5f * (P[base] + Q[base]);
                    o.y += bias[col + 1] + 0.5f * (P[base + 1] + Q[base + 1]);
                }
                *(float2*)&C[base] = o;
            }
        }
    }
}

// ---------------- GCN aggregation (fused self-loop+bias+lrelu) ----------------
template <int F, bool EMIT16>
__global__ void agg_kernel(const float* __restrict__ xw, const float* __restrict__ bias,
                           float* __restrict__ out, __nv_bfloat16* __restrict__ ohi,
                           __nv_bfloat16* __restrict__ olo, int r) {
    int v = blockIdx.x;
    int t = threadIdx.x;  // 128 threads
    constexpr int J = F / 128;
    float acc[J];
#pragma unroll
    for (int j = 0; j < J; j++) acc[j] = 0.0f;

    const int* rp = &g_rowptr[r * (NN + 1)];
    const int* cs = &g_csr_src[r * EE];
    const float* cc = &g_csr_coef[r * EE];

    int beg = rp[v], end = rp[v + 1];
    for (int e = beg; e < end; e++) {
        int s = cs[e];
        float c = cc[e];
#pragma unroll
        for (int j = 0; j < J; j++)
            acc[j] += c * __ldg(&xw[s * F + t + j * 128]);
    }
    float dv = g_dinv[r * NN + v];
    float dv2 = dv * dv;
#pragma unroll
    for (int j = 0; j < J; j++) {
        float val = acc[j] + xw[v * F + t + j * 128] * dv2 + bias[t + j * 128];
        val = (val >= 0.0f) ? val : 0.2f * val;
        if (EMIT16) {
            __nv_bfloat16 h = __float2bfloat16(val);
            ohi[(size_t)v * F + t + j * 128] = h;
            olo[(size_t)v * F + t + j * 128] = __float2bfloat16(val - __bfloat162float(h));
        } else {
            out[(size_t)v * F + t + j * 128] = val;
        }
    }
}

// ---------------- launch ------------------------------------------------------
extern "C" void kernel_launch(void* const* d_in, const int* in_sizes, int n_in,
                              void* d_out, int out_size) {
    const float* x[4] = {(const float*)d_in[0], (const float*)d_in[1],
                         (const float*)d_in[2], (const float*)d_in[3]};
    const void* ed[4] = {d_in[4], d_in[5], d_in[6], d_in[7]};
    const float* W1[4] = {(const float*)d_in[8], (const float*)d_in[10],
                          (const float*)d_in[16], (const float*)d_in[18]};
    const float* B1[4] = {(const float*)d_in[9], (const float*)d_in[11],
                          (const float*)d_in[17], (const float*)d_in[19]};
    const float* W2[4] = {(const float*)d_in[12], (const float*)d_in[14],
                          (const float*)d_in[20], (const float*)d_in[22]};
    const float* B2[4] = {(const float*)d_in[13], (const float*)d_in[15],
                          (const float*)d_in[21], (const float*)d_in[23]};
    float* out = (float*)d_out;

    float *xw1b, *xw2b;
    __nv_bfloat16 *xhi, *xlo, *hhib, *hlob, *whi, *wlo;
    cudaGetSymbolAddress((void**)&xw1b, g_xw1);
    cudaGetSymbolAddress((void**)&xw2b, g_xw2);
    cudaGetSymbolAddress((void**)&xhi, g_Xhi);
    cudaGetSymbolAddress((void**)&xlo, g_Xlo);
    cudaGetSymbolAddress((void**)&hhib, g_Hhi);
    cudaGetSymbolAddress((void**)&hlob, g_Hlo);
    cudaGetSymbolAddress((void**)&whi, g_Whi);
    cudaGetSymbolAddress((void**)&wlo, g_Wlo);

    cudaFuncSetAttribute(gemm_mma, cudaFuncAttributeMaxDynamicSharedMemorySize, SMB_GEMM);

    static cudaStream_t s1 = nullptr, s2 = nullptr, s3 = nullptr;
    static cudaEvent_t evRoot = nullptr, evConv = nullptr, evCSR = nullptr;
    static cudaEvent_t evS2 = nullptr, evS3 = nullptr, evS1J = nullptr;
    if (!s1) {
        cudaStreamCreateWithFlags(&s1, cudaStreamNonBlocking);
        cudaStreamCreateWithFlags(&s2, cudaStreamNonBlocking);
        cudaStreamCreateWithFlags(&s3, cudaStreamNonBlocking);
        cudaEventCreateWithFlags(&evRoot, cudaEventDisableTiming);
        cudaEventCreateWithFlags(&evConv, cudaEventDisableTiming);
        cudaEventCreateWithFlags(&evCSR, cudaEventDisableTiming);
        cudaEventCreateWithFlags(&evS2, cudaEventDisableTiming);
        cudaEventCreateWithFlags(&evS3, cudaEventDisableTiming);
        cudaEventCreateWithFlags(&evS1J, cudaEventDisableTiming);
    }

    // ---- fork: CSR build on s3, conversions on origin ----
    cudaEventRecord(evRoot, 0);
    cudaStreamWaitEvent(s3, evRoot, 0);

    detect_kernel<<<1, 32, 0, s3>>>(ed[0], ed[1], ed[2], ed[3]);
    zero_counts<<<(4 * NN + 255) / 256, 256, 0, s3>>>();
    build_deg<<<dim3((EE + 255) / 256, 4), 256, 0, s3>>>(ed[0], ed[1], ed[2], ed[3]);
    calc_dinv<<<(4 * NN + 255) / 256, 256, 0, s3>>>();
    scan_p1<<<dim3(NCHUNK, 4), CHUNK, 0, s3>>>();
    scan_p2<<<4, 128, 0, s3>>>();
    scan_p3<<<dim3(NCHUNK, 4), CHUNK, 0, s3>>>();
    build_csr<<<dim3((EE + 255) / 256, 4), 256, 0, s3>>>(ed[0], ed[1], ed[2], ed[3]);
    cudaEventRecord(evCSR, s3);

    WArgs wa;
    for (int p = 0; p < 4; p++) {
        wa.W[p] = W1[p];     wa.N[p] = 256;     wa.off[p] = WOFF1(p);
        wa.W[4 + p] = W2[p]; wa.N[4 + p] = 128; wa.off[4 + p] = WOFF2(p);
    }
    wa.W[8] = (const float*)d_in[24]; wa.N[8] = 128; wa.off[8] = WOFFR(0);
    wa.W[9] = (const float*)d_in[26]; wa.N[9] = 128; wa.off[9] = WOFFR(1);
    convW10<<<dim3(256, 10), 256>>>(wa, whi, wlo);

    const int n4 = NN * 256 / 4;
    convA4<<<dim3((n4 + 255) / 256, 4), 256>>>(x[0], x[1], x[2], x[3], xhi, xlo, n4);
    cudaEventRecord(evConv, 0);
    cudaStreamWaitEvent(s1, evConv, 0);
    cudaStreamWaitEvent(s2, evConv, 0);
    cudaStreamWaitEvent(s3, evConv, 0);

    dim3 g1(4, (NN + 127) / 128);   // Ntot=256
    dim3 g2(2, (NN + 127) / 128);   // Ntot=128
    const size_t XSZ = (size_t)NN * 256;
    const size_t X2SZ = (size_t)NN * 128;

    cudaStream_t ps[4] = {(cudaStream_t)0, s1, s2, s3};
    for (int p = 0; p < 4; p++) {
        cudaStream_t st = ps[p];
        float* xw1 = xw1b + p * XSZ;
        float* xw2 = xw2b + p * X2SZ;
        __nv_bfloat16* hhi = hhib + p * XSZ;
        __nv_bfloat16* hlo = hlob + p * XSZ;

        gemm_mma<<<g1, 256, SMB_GEMM, st>>>(xhi + p * XSZ, xlo + p * XSZ, whi + WOFF1(p),
                                            wlo + WOFF1(p), xw1, NN, 256,
                                            nullptr, nullptr, nullptr, 0);
        if (p != 3) cudaStreamWaitEvent(st, evCSR, 0);  // s3 already ordered after CSR
        agg_kernel<256, true><<<NN, 128, 0, st>>>(xw1, B1[p], nullptr, hhi, hlo, p);
        gemm_mma<<<g2, 256, SMB_GEMM, st>>>(hhi, hlo, whi + WOFF2(p), wlo + WOFF2(p), xw2,
                                            NN, 128, nullptr, nullptr, nullptr, 0);
        agg_kernel<128, false><<<NN, 128, 0, st>>>(xw2, B2[p], out + (size_t)(2 + p) * REGSZ,
                                                   nullptr, nullptr, p);
    }

    // ---- join + residual/combine GEMMs ----
    cudaEventRecord(evS2, s2);
    cudaStreamWaitEvent(0, evS2, 0);
    gemm_mma<<<g2, 256, SMB_GEMM>>>(xhi, xlo, whi + WOFFR(0), wlo + WOFFR(0), out, NN, 128,
                                    (const float*)d_in[25], out + (size_t)2 * REGSZ,
                                    out + (size_t)4 * REGSZ, 1);
    cudaEventRecord(evS3, s3);
    cudaStreamWaitEvent(s1, evS3, 0);
    gemm_mma<<<g2, 256, SMB_GEMM, s1>>>(xhi + XSZ, xlo + XSZ, whi + WOFFR(1), wlo + WOFFR(1),
                                        out + (size_t)REGSZ, NN, 128, (const float*)d_in[27],
                                        out + (size_t)3 * REGSZ, out + (size_t)5 * REGSZ, 1);
    cudaEventRecord(evS1J, s1);
    cudaStreamWaitEvent(0, evS1J, 0);
}